// round 4
// baseline (speedup 1.0000x reference)
#include <cuda_runtime.h>

#define N_ATOMS 4096
#define N_PAIRS 4000000
#define CUTOFF 12.0f
#define R_REP 16
#define PAIR_BLOCKS 1184
#define PAIR_THREADS 256
#define N_QUADS (N_PAIRS / 4)

// Replicated force accumulators: R_REP copies of [N_ATOMS][4] floats (~1 MB, L2-resident).
// Zero-initialized at module load; reduce_kernel re-zeroes after each consume.
__device__ float g_scratch[R_REP * N_ATOMS * 4];
__device__ float g_energy;

__device__ __forceinline__ float ld_evict_last(const float* p, unsigned long long policy) {
    float v;
    asm volatile("ld.global.nc.L2::cache_hint.f32 %0, [%1], %2;"
                 : "=f"(v) : "l"(p), "l"(policy));
    return v;
}

__device__ __forceinline__ void do_pair(float d, float B, long ofs,
                                        const float* __restrict__ vector_mat,
                                        float* __restrict__ rep,
                                        int a, int b, float& esum) {
    if (d <= CUTOFF) {
        float invd = 1.0f / d;
        float inv2 = invd * invd;
        float inv6 = inv2 * inv2 * inv2;
        float e = B * inv6;
        esum += e;
        float f = -6.0f * e * invd;

        const float* v = vector_mat + ofs * 3;
        float vx = __ldg(v + 0);
        float vy = __ldg(v + 1);
        float vz = __ldg(v + 2);
        float fx = f * vx, fy = f * vy, fz = f * vz;

        float* pa = rep + a * 4;
        float* pb = rep + b * 4;
        asm volatile("red.global.add.v4.f32 [%0], {%1,%2,%3,%4};"
                     :: "l"(pa), "f"(fx), "f"(fy), "f"(fz), "f"(0.0f) : "memory");
        asm volatile("red.global.add.v4.f32 [%0], {%1,%2,%3,%4};"
                     :: "l"(pb), "f"(-fx), "f"(-fy), "f"(-fz), "f"(0.0f) : "memory");
    }
}

__global__ void __launch_bounds__(PAIR_THREADS) pair_kernel(
    const float* __restrict__ dist_mat,
    const float* __restrict__ vector_mat,
    const float* __restrict__ bcoef,
    const int4*  __restrict__ coord_idx4)   // 2 pairs per int4
{
    int tid = blockIdx.x * blockDim.x + threadIdx.x;
    int stride = gridDim.x * blockDim.x;
    float* rep = g_scratch + (size_t)(blockIdx.x % R_REP) * (N_ATOMS * 4);

    // L2 evict-last policy for dist_mat (64 MB): keep it resident across replays.
    unsigned long long pol;
    asm("createpolicy.fractional.L2::evict_last.b64 %0, 1.0;" : "=l"(pol));

    float esum = 0.0f;

    // 4 pairs per iteration: front-batched loads for MLP.
    for (int i = tid; i < N_QUADS; i += stride) {
        int4 c01 = __ldcs(&coord_idx4[2 * i + 0]);
        int4 c23 = __ldcs(&coord_idx4[2 * i + 1]);
        float4 B = __ldcs((const float4*)bcoef + i);

        long o0 = (long)c01.x * N_ATOMS + c01.y;
        long o1 = (long)c01.z * N_ATOMS + c01.w;
        long o2 = (long)c23.x * N_ATOMS + c23.y;
        long o3 = (long)c23.z * N_ATOMS + c23.w;

        float d0 = ld_evict_last(&dist_mat[o0], pol);
        float d1 = ld_evict_last(&dist_mat[o1], pol);
        float d2 = ld_evict_last(&dist_mat[o2], pol);
        float d3 = ld_evict_last(&dist_mat[o3], pol);

        do_pair(d0, B.x, o0, vector_mat, rep, c01.x, c01.y, esum);
        do_pair(d1, B.y, o1, vector_mat, rep, c01.z, c01.w, esum);
        do_pair(d2, B.z, o2, vector_mat, rep, c23.x, c23.y, esum);
        do_pair(d3, B.w, o3, vector_mat, rep, c23.z, c23.w, esum);
    }

    // Energy: warp reduce -> block reduce -> one atomic per block.
    #pragma unroll
    for (int o = 16; o > 0; o >>= 1)
        esum += __shfl_xor_sync(0xffffffffu, esum, o);

    __shared__ float warp_s[PAIR_THREADS / 32];
    int lane = threadIdx.x & 31;
    int wid  = threadIdx.x >> 5;
    if (lane == 0) warp_s[wid] = esum;
    __syncthreads();
    if (wid == 0) {
        float v = (lane < (PAIR_THREADS / 32)) ? warp_s[lane] : 0.0f;
        #pragma unroll
        for (int o = 16; o > 0; o >>= 1)
            v += __shfl_xor_sync(0xffffffffu, v, o);
        if (lane == 0) atomicAdd(&g_energy, v);
    }
}

// Consumes scratch + energy, writes full output, and re-zeroes scratch/energy
// so the next graph replay starts clean (no separate zero kernel needed).
__global__ void reduce_kernel(const float* __restrict__ forces_in, float* __restrict__ d_out) {
    int a = blockIdx.x * blockDim.x + threadIdx.x;
    if (a == 0) {
        d_out[0] = g_energy;
        g_energy = 0.0f;
    }
    if (a < N_ATOMS) {
        float fx = 0.0f, fy = 0.0f, fz = 0.0f;
        #pragma unroll
        for (int r = 0; r < R_REP; r++) {
            float4* p = reinterpret_cast<float4*>(
                g_scratch + (size_t)r * N_ATOMS * 4 + a * 4);
            const float4 v = *p;
            fx += v.x; fy += v.y; fz += v.z;
            *p = make_float4(0.0f, 0.0f, 0.0f, 0.0f);
        }
        d_out[1 + a * 3 + 0] = forces_in[a * 3 + 0] + fx;
        d_out[1 + a * 3 + 1] = forces_in[a * 3 + 1] + fy;
        d_out[1 + a * 3 + 2] = forces_in[a * 3 + 2] + fz;
    }
}

extern "C" void kernel_launch(void* const* d_in, const int* in_sizes, int n_in,
                              void* d_out, int out_size) {
    const float* dist_mat   = (const float*)d_in[0];   // (4096, 4096) f32
    const float* vector_mat = (const float*)d_in[1];   // (4096, 4096, 3) f32
    const float* forces_in  = (const float*)d_in[2];   // (4096, 3) f32 zeros
    const float* bcoef      = (const float*)d_in[3];   // (N_PAIRS,) f32
    const int4*  coord_idx4 = (const int4*)d_in[4];    // (N_PAIRS, 2) i32, 2 pairs per int4

    float* out = (float*)d_out;                        // [energy, forces(4096*3)]

    pair_kernel<<<PAIR_BLOCKS, PAIR_THREADS>>>(dist_mat, vector_mat, bcoef, coord_idx4);
    reduce_kernel<<<(N_ATOMS + 255) / 256, 256>>>(forces_in, out);
}

// round 5
// speedup vs baseline: 1.0019x; 1.0019x over previous
#include <cuda_runtime.h>

#define N_ATOMS 4096
#define N_PAIRS 4000000
#define CUTOFF 12.0f
#define R_REP 16
#define PAIR_BLOCKS 1184
#define PAIR_THREADS 256
#define N_QUADS (N_PAIRS / 4)

// Replicated force accumulators: R_REP copies of [N_ATOMS][4] floats (~1 MB, L2-resident).
// Zero-initialized at module load; reduce_kernel re-zeroes after each consume.
__device__ float g_scratch[R_REP * N_ATOMS * 4];
__device__ float g_energy;

__device__ __forceinline__ void do_pair(float d, float B, long ofs,
                                        const float* __restrict__ vector_mat,
                                        float* __restrict__ rep,
                                        int a, int b, float& esum) {
    if (d <= CUTOFF) {
        float invd = 1.0f / d;
        float inv2 = invd * invd;
        float inv6 = inv2 * inv2 * inv2;
        float e = B * inv6;
        esum += e;
        float f = -6.0f * e * invd;

        // vec load in 2 wavefronts instead of 3: addr = ofs*12 is 8B-aligned
        // iff ofs is even. Pick {f2,f1} or {f1,f2} split by parity.
        const float* v = vector_mat + ofs * 3;
        float vx, vy, vz;
        if ((int)ofs & 1) {
            vx = __ldg(v);
            float2 t = __ldg((const float2*)(v + 1));   // addr+4 is 8B-aligned
            vy = t.x; vz = t.y;
        } else {
            float2 t = __ldg((const float2*)v);          // addr is 8B-aligned
            vx = t.x; vy = t.y;
            vz = __ldg(v + 2);
        }
        float fx = f * vx, fy = f * vy, fz = f * vz;

        float* pa = rep + a * 4;
        float* pb = rep + b * 4;
        asm volatile("red.global.add.v4.f32 [%0], {%1,%2,%3,%4};"
                     :: "l"(pa), "f"(fx), "f"(fy), "f"(fz), "f"(0.0f) : "memory");
        asm volatile("red.global.add.v4.f32 [%0], {%1,%2,%3,%4};"
                     :: "l"(pb), "f"(-fx), "f"(-fy), "f"(-fz), "f"(0.0f) : "memory");
    }
}

__global__ void __launch_bounds__(PAIR_THREADS) pair_kernel(
    const float* __restrict__ dist_mat,
    const float* __restrict__ vector_mat,
    const float* __restrict__ bcoef,
    const int4*  __restrict__ coord_idx4)   // 2 pairs per int4
{
    int tid = blockIdx.x * blockDim.x + threadIdx.x;
    int stride = gridDim.x * blockDim.x;
    float* rep = g_scratch + (size_t)(blockIdx.x % R_REP) * (N_ATOMS * 4);

    float esum = 0.0f;

    for (int i = tid; i < N_QUADS; i += stride) {
        int4 c01 = __ldcs(&coord_idx4[2 * i + 0]);
        int4 c23 = __ldcs(&coord_idx4[2 * i + 1]);
        float4 B = __ldcs((const float4*)bcoef + i);

        long o0 = (long)c01.x * N_ATOMS + c01.y;
        long o1 = (long)c01.z * N_ATOMS + c01.w;
        long o2 = (long)c23.x * N_ATOMS + c23.y;
        long o3 = (long)c23.z * N_ATOMS + c23.w;

        float d0 = __ldg(&dist_mat[o0]);
        float d1 = __ldg(&dist_mat[o1]);
        float d2 = __ldg(&dist_mat[o2]);
        float d3 = __ldg(&dist_mat[o3]);

        do_pair(d0, B.x, o0, vector_mat, rep, c01.x, c01.y, esum);
        do_pair(d1, B.y, o1, vector_mat, rep, c01.z, c01.w, esum);
        do_pair(d2, B.z, o2, vector_mat, rep, c23.x, c23.y, esum);
        do_pair(d3, B.w, o3, vector_mat, rep, c23.z, c23.w, esum);
    }

    // Energy: warp reduce -> block reduce -> one atomic per block.
    #pragma unroll
    for (int o = 16; o > 0; o >>= 1)
        esum += __shfl_xor_sync(0xffffffffu, esum, o);

    __shared__ float warp_s[PAIR_THREADS / 32];
    int lane = threadIdx.x & 31;
    int wid  = threadIdx.x >> 5;
    if (lane == 0) warp_s[wid] = esum;
    __syncthreads();
    if (wid == 0) {
        float v = (lane < (PAIR_THREADS / 32)) ? warp_s[lane] : 0.0f;
        #pragma unroll
        for (int o = 16; o > 0; o >>= 1)
            v += __shfl_xor_sync(0xffffffffu, v, o);
        if (lane == 0) atomicAdd(&g_energy, v);
    }
}

// One thread per (atom, rep-quad): 4 independent float4 loads each, shuffle-
// reduce across 4 adjacent lanes. Re-zeroes scratch/energy for next replay.
__global__ void reduce_kernel(const float* __restrict__ forces_in, float* __restrict__ d_out) {
    int idx = blockIdx.x * blockDim.x + threadIdx.x;   // 0 .. 4*N_ATOMS-1
    int a  = idx >> 2;
    int rs = idx & 3;

    float fx = 0.0f, fy = 0.0f, fz = 0.0f;
    #pragma unroll
    for (int k = 0; k < R_REP / 4; k++) {
        int r = rs + k * 4;
        float4* p = reinterpret_cast<float4*>(
            g_scratch + ((size_t)r * N_ATOMS + a) * 4);
        const float4 v = *p;
        fx += v.x; fy += v.y; fz += v.z;
        *p = make_float4(0.0f, 0.0f, 0.0f, 0.0f);
    }

    fx += __shfl_xor_sync(0xffffffffu, fx, 1);
    fy += __shfl_xor_sync(0xffffffffu, fy, 1);
    fz += __shfl_xor_sync(0xffffffffu, fz, 1);
    fx += __shfl_xor_sync(0xffffffffu, fx, 2);
    fy += __shfl_xor_sync(0xffffffffu, fy, 2);
    fz += __shfl_xor_sync(0xffffffffu, fz, 2);

    if (rs == 0) {
        d_out[1 + a * 3 + 0] = forces_in[a * 3 + 0] + fx;
        d_out[1 + a * 3 + 1] = forces_in[a * 3 + 1] + fy;
        d_out[1 + a * 3 + 2] = forces_in[a * 3 + 2] + fz;
    }
    if (idx == 0) {
        d_out[0] = g_energy;
        g_energy = 0.0f;
    }
}

extern "C" void kernel_launch(void* const* d_in, const int* in_sizes, int n_in,
                              void* d_out, int out_size) {
    const float* dist_mat   = (const float*)d_in[0];   // (4096, 4096) f32
    const float* vector_mat = (const float*)d_in[1];   // (4096, 4096, 3) f32
    const float* forces_in  = (const float*)d_in[2];   // (4096, 3) f32 zeros
    const float* bcoef      = (const float*)d_in[3];   // (N_PAIRS,) f32
    const int4*  coord_idx4 = (const int4*)d_in[4];    // (N_PAIRS, 2) i32, 2 pairs per int4

    float* out = (float*)d_out;                        // [energy, forces(4096*3)]

    pair_kernel<<<PAIR_BLOCKS, PAIR_THREADS>>>(dist_mat, vector_mat, bcoef, coord_idx4);
    reduce_kernel<<<(4 * N_ATOMS) / 256, 256>>>(forces_in, out);
}